// round 1
// baseline (speedup 1.0000x reference)
#include <cuda_runtime.h>
#include <math.h>
#include <float.h>

// ProbSparse attention (Informer) for B=2,H=8,L=4096,D=64, sample_k=u=45.
// Pipeline:
//   1) cumsum of V along L (3-pass chunked scan) -> writes full output
//   2) M[bh,q] = max_s(QK_s) - sum_s(QK_s)/L  over 45 sampled keys
//   3) top-45 of M per (b,h)  (tie: lower index, matching jax.lax.top_k)
//   4) split-KV attention for the 45 selected queries (causal mask k<=pos)
//   5) combine partials + scatter into output rows
//
// All scratch is __device__ global (no allocation anywhere). Graph-capturable:
// kernel launches only, single (legacy default) stream, deterministic.

#define BH      16
#define LSEQ    4096
#define DIM     64
#define NSAMP   45
#define NTOP    45
#define NSPLIT  64                 // keys per split = 64
#define KPS     (LSEQ / NSPLIT)    // 64
#define NCHUNK  128                // cumsum chunks
#define RPC     (LSEQ / NCHUNK)    // 32 rows per chunk

// ---------------- device scratch ----------------
__device__ float g_M[BH * LSEQ];                     // 1 MB
__device__ int   g_top[BH * NTOP];
__device__ float g_pm[BH * NSPLIT * NTOP];           // partial max
__device__ float g_pl[BH * NSPLIT * NTOP];           // partial sum(exp)
__device__ float g_po[BH * NSPLIT * NTOP * DIM];     // partial o  (~11.8 MB)
__device__ float g_csum[BH * NCHUNK * DIM];          // chunk sums / prefixes

// ---------------- cumsum pass 1: per-chunk column sums ----------------
__global__ __launch_bounds__(256) void cumsum1(const float* __restrict__ V) {
    int t = threadIdx.x;
    int d = t & 63;
    int cib = t >> 6;                      // 0..3 chunks per block
    int blk = blockIdx.x;                  // BH*32 blocks
    int bh = blk >> 5;
    int chunk = (blk & 31) * 4 + cib;      // 0..127
    const float* p = V + ((size_t)bh * LSEQ + (size_t)chunk * RPC) * DIM + d;
    float s = 0.f;
#pragma unroll
    for (int r = 0; r < RPC; r++) s += p[r * DIM];
    g_csum[(bh * NCHUNK + chunk) * DIM + d] = s;
}

// ---------------- cumsum pass 2: exclusive scan of chunk sums ----------------
__global__ __launch_bounds__(256) void cumsum2() {
    __shared__ float s[NCHUNK * DIM];      // 32 KB
    int bh = blockIdx.x;
    for (int i = threadIdx.x; i < NCHUNK * DIM; i += 256)
        s[i] = g_csum[bh * NCHUNK * DIM + i];
    __syncthreads();
    if (threadIdx.x < DIM) {
        int d = threadIdx.x;
        float acc = 0.f;
#pragma unroll 4
        for (int c = 0; c < NCHUNK; c++) {
            float v = s[c * DIM + d];
            g_csum[(bh * NCHUNK + c) * DIM + d] = acc;   // exclusive prefix
            acc += v;
        }
    }
}

// ---------------- cumsum pass 3: write inclusive cumsum ----------------
__global__ __launch_bounds__(256) void cumsum3(const float* __restrict__ V,
                                               float* __restrict__ out) {
    int t = threadIdx.x;
    int d = t & 63;
    int cib = t >> 6;
    int blk = blockIdx.x;
    int bh = blk >> 5;
    int chunk = (blk & 31) * 4 + cib;
    const float* p = V + ((size_t)bh * LSEQ + (size_t)chunk * RPC) * DIM + d;
    float* o = out + ((size_t)bh * LSEQ + (size_t)chunk * RPC) * DIM + d;
    float acc = g_csum[(bh * NCHUNK + chunk) * DIM + d];
#pragma unroll
    for (int r = 0; r < RPC; r++) {
        acc += p[r * DIM];
        o[r * DIM] = acc;
    }
}

// ---------------- M computation: warp per query ----------------
__global__ __launch_bounds__(256) void computeM(const float* __restrict__ Q,
                                                const float* __restrict__ K,
                                                const int* __restrict__ idx) {
    int w = threadIdx.x >> 5;
    int lane = threadIdx.x & 31;
    int blk = blockIdx.x;                  // BH * 512 blocks
    int bh = blk >> 9;
    int q = (blk & 511) * 8 + w;

    const float2* qp = (const float2*)(Q + ((size_t)bh * LSEQ + q) * DIM);
    float2 qv = qp[lane];
    const int* ip = idx + q * NSAMP;
    const float* Kbh = K + (size_t)bh * LSEQ * DIM;

    float mx = -FLT_MAX, sm = 0.f;
    // 45 = 15 groups of 3: 3-way MLP for latency hiding
#pragma unroll 3
    for (int s = 0; s < NSAMP; s += 3) {
        int k0 = ip[s], k1 = ip[s + 1], k2 = ip[s + 2];
        float2 a = ((const float2*)(Kbh + (size_t)k0 * DIM))[lane];
        float2 b = ((const float2*)(Kbh + (size_t)k1 * DIM))[lane];
        float2 c = ((const float2*)(Kbh + (size_t)k2 * DIM))[lane];
        float p0 = qv.x * a.x + qv.y * a.y;
        float p1 = qv.x * b.x + qv.y * b.y;
        float p2 = qv.x * c.x + qv.y * c.y;
#pragma unroll
        for (int o = 16; o; o >>= 1) {
            p0 += __shfl_xor_sync(0xffffffffu, p0, o);
            p1 += __shfl_xor_sync(0xffffffffu, p1, o);
            p2 += __shfl_xor_sync(0xffffffffu, p2, o);
        }
        mx = fmaxf(mx, p0); sm += p0;
        mx = fmaxf(mx, p1); sm += p1;
        mx = fmaxf(mx, p2); sm += p2;
    }
    if (lane == 0)
        g_M[bh * LSEQ + q] = mx - sm * (1.0f / (float)LSEQ);
}

// ---------------- top-k (k=45) per bh ----------------
__global__ __launch_bounds__(1024) void topk_kernel() {
    __shared__ float sv[LSEQ];             // 16 KB
    __shared__ float rv[32];
    __shared__ int ri[32];
    int bh = blockIdx.x;
    int t = threadIdx.x;
    for (int i = t; i < LSEQ; i += 1024) sv[i] = g_M[bh * LSEQ + i];
    __syncthreads();

    for (int it = 0; it < NTOP; it++) {
        float bv = -FLT_MAX;
        int bi = LSEQ;                     // sentinel: never preferred on tie
#pragma unroll
        for (int rpt = 0; rpt < 4; rpt++) {
            int i = t + rpt * 1024;
            float v = sv[i];
            if (v > bv || (v == bv && i < bi)) { bv = v; bi = i; }
        }
#pragma unroll
        for (int o = 16; o; o >>= 1) {
            float ov = __shfl_xor_sync(0xffffffffu, bv, o);
            int oi = __shfl_xor_sync(0xffffffffu, bi, o);
            if (ov > bv || (ov == bv && oi < bi)) { bv = ov; bi = oi; }
        }
        if ((t & 31) == 0) { rv[t >> 5] = bv; ri[t >> 5] = bi; }
        __syncthreads();
        if (t < 32) {
            bv = rv[t]; bi = ri[t];
#pragma unroll
            for (int o = 16; o; o >>= 1) {
                float ov = __shfl_xor_sync(0xffffffffu, bv, o);
                int oi = __shfl_xor_sync(0xffffffffu, bi, o);
                if (ov > bv || (ov == bv && oi < bi)) { bv = ov; bi = oi; }
            }
            if (t == 0) { g_top[bh * NTOP + it] = bi; sv[bi] = -FLT_MAX; }
        }
        __syncthreads();
    }
}

// ---------------- split-KV attention partials ----------------
// grid = BH * NSPLIT blocks of 256 threads; each block: one 64-key tile,
// all 45 selected queries.
__global__ __launch_bounds__(256) void attn_partial(const float* __restrict__ Q,
                                                    const float* __restrict__ K,
                                                    const float* __restrict__ V) {
    __shared__ float sK[64 * 68];          // padded K tile (17.4 KB)
    __shared__ float sQ[48 * 68];          // padded Q rows (13 KB)
    __shared__ float sP[NTOP * 64];        // scores -> probs (11.5 KB)
    __shared__ int   sTop[NTOP];

    int t = threadIdx.x;
    int blk = blockIdx.x;
    int bh = blk >> 6;
    int sp = blk & 63;
    int k0 = sp * KPS;

    if (t < NTOP) sTop[t] = g_top[bh * NTOP + t];
    __syncthreads();

    // Load K tile (contiguous 16 KB, coalesced)
    const float* Kp = K + ((size_t)bh * LSEQ + k0) * DIM;
    for (int i = t; i < 64 * 64; i += 256) {
        int r = i >> 6, d = i & 63;
        sK[r * 68 + d] = Kp[i];
    }
    // Load 45 Q rows (gathered, 256B each, coalesced per row segment)
    for (int i = t; i < NTOP * 64; i += 256) {
        int u = i >> 6, d = i & 63;
        sQ[u * 68 + d] = Q[((size_t)bh * LSEQ + sTop[u]) * DIM + d];
    }
    __syncthreads();

    // Scores: thread (g, kk), g = t>>6 in 0..3, kk = t&63
    int g = t >> 6;
    int kk = t & 63;
#pragma unroll
    for (int j = 0; j < 12; j++) {
        int u = g + 4 * j;
        if (u >= NTOP) break;
        float acc;
        if (k0 + kk > sTop[u]) {
            acc = -FLT_MAX;                // causal mask
        } else {
            acc = 0.f;
            const float4* qa = (const float4*)(sQ + u * 68);
            const float4* ka = (const float4*)(sK + kk * 68);
#pragma unroll
            for (int dd = 0; dd < 16; dd++) {
                float4 a = qa[dd], b = ka[dd];
                acc += a.x * b.x + a.y * b.y + a.z * b.z + a.w * b.w;
            }
            acc *= 0.125f;                 // 1/sqrt(64)
        }
        sP[u * 64 + kk] = acc;
    }
    __syncthreads();

    // Per-u softmax stats within this split: warp per u
    int w = t >> 5, lane = t & 31;
    for (int u = w; u < NTOP; u += 8) {
        float a = sP[u * 64 + lane];
        float b = sP[u * 64 + lane + 32];
        float m = fmaxf(a, b);
#pragma unroll
        for (int o = 16; o; o >>= 1) m = fmaxf(m, __shfl_xor_sync(0xffffffffu, m, o));
        float e0 = __expf(a - m);
        float e1 = __expf(b - m);
        float l = e0 + e1;
#pragma unroll
        for (int o = 16; o; o >>= 1) l += __shfl_xor_sync(0xffffffffu, l, o);
        sP[u * 64 + lane] = e0;
        sP[u * 64 + lane + 32] = e1;
        if (lane == 0) {
            g_pm[(bh * NSPLIT + sp) * NTOP + u] = m;
            g_pl[(bh * NSPLIT + sp) * NTOP + u] = l;
        }
    }
    __syncthreads();

    // o accumulation: thread (g, d): o_u for u = g + 4j, d = t&63
    int d = t & 63;
    float oacc[12];
#pragma unroll
    for (int j = 0; j < 12; j++) oacc[j] = 0.f;
    const float* Vp = V + ((size_t)bh * LSEQ + k0) * DIM + d;
    for (int k4 = 0; k4 < 64; k4 += 4) {
        float v0 = Vp[(k4 + 0) * DIM];
        float v1 = Vp[(k4 + 1) * DIM];
        float v2 = Vp[(k4 + 2) * DIM];
        float v3 = Vp[(k4 + 3) * DIM];
#pragma unroll
        for (int j = 0; j < 12; j++) {
            int u = g + 4 * j;
            if (u < NTOP) {
                float4 pv = *(const float4*)&sP[u * 64 + k4];   // broadcast LDS.128
                oacc[j] += pv.x * v0 + pv.y * v1 + pv.z * v2 + pv.w * v3;
            }
        }
    }
    float* po = g_po + (size_t)(bh * NSPLIT + sp) * NTOP * DIM;
#pragma unroll
    for (int j = 0; j < 12; j++) {
        int u = g + 4 * j;
        if (u < NTOP) po[u * DIM + d] = oacc[j];
    }
}

// ---------------- combine partials + scatter ----------------
__global__ __launch_bounds__(64) void combine_kernel(float* __restrict__ out) {
    int blk = blockIdx.x;                  // BH * NTOP
    int bh = blk / NTOP;
    int u = blk % NTOP;
    int d = threadIdx.x;

    const float* pm = g_pm + bh * NSPLIT * NTOP + u;
    const float* pl = g_pl + bh * NSPLIT * NTOP + u;

    float m = -FLT_MAX;
#pragma unroll 4
    for (int sp = 0; sp < NSPLIT; sp++) m = fmaxf(m, pm[sp * NTOP]);

    float acc = 0.f, l = 0.f;
    const float* po = g_po + ((size_t)bh * NSPLIT * NTOP + u) * DIM + d;
#pragma unroll 4
    for (int sp = 0; sp < NSPLIT; sp++) {
        float wgt = __expf(pm[sp * NTOP] - m);
        l += wgt * pl[sp * NTOP];
        acc += wgt * po[(size_t)sp * NTOP * DIM];
    }
    int row = g_top[bh * NTOP + u];
    out[((size_t)bh * LSEQ + row) * DIM + d] = acc / l;
}

// ---------------- launch ----------------
extern "C" void kernel_launch(void* const* d_in, const int* in_sizes, int n_in,
                              void* d_out, int out_size) {
    const float* Q = (const float*)d_in[0];
    const float* K = (const float*)d_in[1];
    const float* V = (const float*)d_in[2];
    const int* idx = (const int*)d_in[3];
    float* out = (float*)d_out;

    cumsum1<<<BH * 32, 256>>>(V);
    cumsum2<<<BH, 256>>>();
    cumsum3<<<BH * 32, 256>>>(V, out);

    computeM<<<BH * 512, 256>>>(Q, K, idx);
    topk_kernel<<<BH, 1024>>>();
    attn_partial<<<BH * NSPLIT, 256>>>(Q, K, V);
    combine_kernel<<<BH * NTOP, 64>>>(out);
}

// round 2
// speedup vs baseline: 1.3133x; 1.3133x over previous
#include <cuda_runtime.h>
#include <cuda_fp16.h>
#include <math.h>
#include <float.h>

// ProbSparse attention (Informer) B=2,H=8,L=4096,D=64, u=45.
// Round 2: fp16-K sampling pass (1 wavefront/row, 4 rows/warp, cheap reduce),
// two-stage exact top-k via 384 candidates, register-tiled attention.

#define BH      16
#define LSEQ    4096
#define DIM     64
#define NSAMP   45
#define NTOP    45
#define NCAND   384                // 32 warps x 12 local winners
#define NSPLIT  64
#define KPS     (LSEQ / NSPLIT)    // 64
#define NCHUNK  128
#define RPC     (LSEQ / NCHUNK)    // 32

// ---------------- device scratch ----------------
__device__ __half g_Kh[BH * LSEQ * DIM];             // 8 MB fp16 K
__device__ float  g_M[BH * LSEQ];                    // approx M
__device__ int    g_cand[BH * NCAND];
__device__ float  g_Mex[BH * NCAND];                 // exact M for candidates
__device__ int    g_top[BH * NTOP];
__device__ float  g_pm[BH * NSPLIT * NTOP];
__device__ float  g_pl[BH * NSPLIT * NTOP];
__device__ float  g_po[BH * NSPLIT * NTOP * DIM];
__device__ float  g_csum[BH * NCHUNK * DIM];

// ---------------- K fp32 -> fp16 ----------------
__global__ __launch_bounds__(256) void convertK(const float* __restrict__ K) {
    int i = blockIdx.x * 256 + threadIdx.x;           // x4 elements
    float4 v = ((const float4*)K)[i];
    __half2 h0 = __floats2half2_rn(v.x, v.y);
    __half2 h1 = __floats2half2_rn(v.z, v.w);
    uint2 packed;
    packed.x = *(unsigned int*)&h0;
    packed.y = *(unsigned int*)&h1;
    ((uint2*)g_Kh)[i] = packed;
}

// ---------------- cumsum passes ----------------
__global__ __launch_bounds__(256) void cumsum1(const float* __restrict__ V) {
    int t = threadIdx.x, d = t & 63, cib = t >> 6;
    int blk = blockIdx.x, bh = blk >> 5;
    int chunk = (blk & 31) * 4 + cib;
    const float* p = V + ((size_t)bh * LSEQ + (size_t)chunk * RPC) * DIM + d;
    float s = 0.f;
#pragma unroll
    for (int r = 0; r < RPC; r++) s += p[r * DIM];
    g_csum[(bh * NCHUNK + chunk) * DIM + d] = s;
}

__global__ __launch_bounds__(256) void cumsum2() {
    __shared__ float s[NCHUNK * DIM];
    int bh = blockIdx.x;
    for (int i = threadIdx.x; i < NCHUNK * DIM; i += 256)
        s[i] = g_csum[bh * NCHUNK * DIM + i];
    __syncthreads();
    if (threadIdx.x < DIM) {
        int d = threadIdx.x;
        float acc = 0.f;
#pragma unroll 4
        for (int c = 0; c < NCHUNK; c++) {
            float v = s[c * DIM + d];
            g_csum[(bh * NCHUNK + c) * DIM + d] = acc;
            acc += v;
        }
    }
}

__global__ __launch_bounds__(256) void cumsum3(const float* __restrict__ V,
                                               float* __restrict__ out) {
    int t = threadIdx.x, d = t & 63, cib = t >> 6;
    int blk = blockIdx.x, bh = blk >> 5;
    int chunk = (blk & 31) * 4 + cib;
    const float* p = V + ((size_t)bh * LSEQ + (size_t)chunk * RPC) * DIM + d;
    float* o = out + ((size_t)bh * LSEQ + (size_t)chunk * RPC) * DIM + d;
    float acc = g_csum[(bh * NCHUNK + chunk) * DIM + d];
#pragma unroll
    for (int r = 0; r < RPC; r++) {
        acc += p[r * DIM];
        o[r * DIM] = acc;
    }
}

// ---------------- approx M: fp16 K gather, 4 rows/warp, 8 lanes/row --------
__global__ __launch_bounds__(256) void computeM_approx(const float* __restrict__ Q,
                                                       const int* __restrict__ idx) {
    int w = threadIdx.x >> 5;
    int lane = threadIdx.x & 31;
    int r = lane >> 3;                 // row slot 0..3
    int sub = lane & 7;                // 8B-halves slice within row
    int blk = blockIdx.x;
    int bh = blk >> 9;
    int q = (blk & 511) * 8 + w;

    // q slice: 8 floats at d = sub*8..sub*8+7
    const float4* qp = (const float4*)(Q + ((size_t)bh * LSEQ + q) * DIM);
    float4 qa = qp[sub * 2];
    float4 qb = qp[sub * 2 + 1];

    const int* ip = idx + q * NSAMP;
    int i0 = ip[lane < NSAMP ? lane : 0];
    int i1 = ip[lane < (NSAMP - 32) ? 32 + lane : 0];

    const __half* Kbh = g_Kh + (size_t)bh * LSEQ * DIM;

    float mx = -FLT_MAX, sm = 0.f;

#pragma unroll
    for (int i = 0; i < 11; i++) {
        int j = 4 * i + r;             // sample index for this slot
        int kidx;
        if (i < 8) kidx = __shfl_sync(0xffffffffu, i0, j);
        else       kidx = __shfl_sync(0xffffffffu, i1, j - 32);
        uint4 kv = *(const uint4*)(Kbh + (size_t)kidx * DIM + sub * 8);
        float2 f0 = __half22float2(*(__half2*)&kv.x);
        float2 f1 = __half22float2(*(__half2*)&kv.y);
        float2 f2 = __half22float2(*(__half2*)&kv.z);
        float2 f3 = __half22float2(*(__half2*)&kv.w);
        float p = qa.x * f0.x + qa.y * f0.y + qa.z * f1.x + qa.w * f1.y
                + qb.x * f2.x + qb.y * f2.y + qb.z * f3.x + qb.w * f3.y;
        p += __shfl_xor_sync(0xffffffffu, p, 1);
        p += __shfl_xor_sync(0xffffffffu, p, 2);
        p += __shfl_xor_sync(0xffffffffu, p, 4);
        mx = fmaxf(mx, p);
        sm += p;
    }
    // tail sample 44 (slot 0 only accumulates)
    {
        int kidx = __shfl_sync(0xffffffffu, i1, 12);   // 44-32
        uint4 kv = *(const uint4*)(Kbh + (size_t)kidx * DIM + sub * 8);
        float2 f0 = __half22float2(*(__half2*)&kv.x);
        float2 f1 = __half22float2(*(__half2*)&kv.y);
        float2 f2 = __half22float2(*(__half2*)&kv.z);
        float2 f3 = __half22float2(*(__half2*)&kv.w);
        float p = qa.x * f0.x + qa.y * f0.y + qa.z * f1.x + qa.w * f1.y
                + qb.x * f2.x + qb.y * f2.y + qb.z * f3.x + qb.w * f3.y;
        p += __shfl_xor_sync(0xffffffffu, p, 1);
        p += __shfl_xor_sync(0xffffffffu, p, 2);
        p += __shfl_xor_sync(0xffffffffu, p, 4);
        if (r == 0) { mx = fmaxf(mx, p); sm += p; }
    }
    // cross-slot reduce
    mx = fmaxf(mx, __shfl_xor_sync(0xffffffffu, mx, 8));
    mx = fmaxf(mx, __shfl_xor_sync(0xffffffffu, mx, 16));
    sm += __shfl_xor_sync(0xffffffffu, sm, 8);
    sm += __shfl_xor_sync(0xffffffffu, sm, 16);
    if (lane == 0)
        g_M[bh * LSEQ + q] = mx - sm * (1.0f / (float)LSEQ);
}

// ---------------- candidates: per-warp local top-12 ----------------
__global__ __launch_bounds__(1024) void candidates() {
    int bh = blockIdx.x;
    int t = threadIdx.x;
    int w = t >> 5, lane = t & 31;
    int base = w * 128;
    float v[4];
#pragma unroll
    for (int rr = 0; rr < 4; rr++)
        v[rr] = g_M[bh * LSEQ + base + lane + 32 * rr];

    for (int it = 0; it < 12; it++) {
        float bv = v[0];
        int bi = base + lane;
#pragma unroll
        for (int rr = 1; rr < 4; rr++) {
            float vv = v[rr];
            int ii = base + lane + 32 * rr;
            if (vv > bv) { bv = vv; bi = ii; }   // lower idx wins ties (rr asc)
        }
#pragma unroll
        for (int o = 16; o; o >>= 1) {
            float ov = __shfl_xor_sync(0xffffffffu, bv, o);
            int oi = __shfl_xor_sync(0xffffffffu, bi, o);
            if (ov > bv || (ov == bv && oi < bi)) { bv = ov; bi = oi; }
        }
        int loc = bi - base;
        if ((loc & 31) == lane) v[loc >> 5] = -FLT_MAX;
        if (lane == 0) g_cand[bh * NCAND + w * 12 + it] = bi;
    }
}

// ---------------- exact fp32 M for candidates (warp per candidate) ---------
__global__ __launch_bounds__(256) void refineM(const float* __restrict__ Q,
                                               const float* __restrict__ K,
                                               const int* __restrict__ idx) {
    int w = threadIdx.x >> 5;
    int lane = threadIdx.x & 31;
    int blk = blockIdx.x;               // BH * 48
    int bh = blk / 48;
    int slot = (blk % 48) * 8 + w;
    int q = g_cand[bh * NCAND + slot];

    const float2* qp = (const float2*)(Q + ((size_t)bh * LSEQ + q) * DIM);
    float2 qv = qp[lane];
    const int* ip = idx + q * NSAMP;
    const float* Kbh = K + (size_t)bh * LSEQ * DIM;

    float mx = -FLT_MAX, sm = 0.f;
#pragma unroll 3
    for (int s = 0; s < NSAMP; s += 3) {
        int k0 = ip[s], k1 = ip[s + 1], k2 = ip[s + 2];
        float2 a = ((const float2*)(Kbh + (size_t)k0 * DIM))[lane];
        float2 b = ((const float2*)(Kbh + (size_t)k1 * DIM))[lane];
        float2 c = ((const float2*)(Kbh + (size_t)k2 * DIM))[lane];
        float p0 = qv.x * a.x + qv.y * a.y;
        float p1 = qv.x * b.x + qv.y * b.y;
        float p2 = qv.x * c.x + qv.y * c.y;
#pragma unroll
        for (int o = 16; o; o >>= 1) {
            p0 += __shfl_xor_sync(0xffffffffu, p0, o);
            p1 += __shfl_xor_sync(0xffffffffu, p1, o);
            p2 += __shfl_xor_sync(0xffffffffu, p2, o);
        }
        mx = fmaxf(mx, p0); sm += p0;
        mx = fmaxf(mx, p1); sm += p1;
        mx = fmaxf(mx, p2); sm += p2;
    }
    if (lane == 0)
        g_Mex[bh * NCAND + slot] = mx - sm * (1.0f / (float)LSEQ);
}

// ---------------- final exact top-45 among candidates ----------------
__global__ __launch_bounds__(NCAND) void topk_final() {
    __shared__ float wv[12];
    __shared__ int wi[12], ws[12], winslot;
    int bh = blockIdx.x;
    int t = threadIdx.x;
    int lane = t & 31, w = t >> 5;

    float myv = g_Mex[bh * NCAND + t];
    int myi = g_cand[bh * NCAND + t];

    for (int it = 0; it < NTOP; it++) {
        float bv = myv; int bi = myi; int bs = t;
#pragma unroll
        for (int o = 16; o; o >>= 1) {
            float ov = __shfl_xor_sync(0xffffffffu, bv, o);
            int oi = __shfl_xor_sync(0xffffffffu, bi, o);
            int os = __shfl_xor_sync(0xffffffffu, bs, o);
            if (ov > bv || (ov == bv && oi < bi)) { bv = ov; bi = oi; bs = os; }
        }
        if (lane == 0) { wv[w] = bv; wi[w] = bi; ws[w] = bs; }
        __syncthreads();
        if (t < 32) {
            float v2 = (t < 12) ? wv[t] : -FLT_MAX;
            int i2 = (t < 12) ? wi[t] : 0x7fffffff;
            int s2 = (t < 12) ? ws[t] : 0;
#pragma unroll
            for (int o = 16; o; o >>= 1) {
                float ov = __shfl_xor_sync(0xffffffffu, v2, o);
                int oi = __shfl_xor_sync(0xffffffffu, i2, o);
                int os = __shfl_xor_sync(0xffffffffu, s2, o);
                if (ov > v2 || (ov == v2 && oi < i2)) { v2 = ov; i2 = oi; s2 = os; }
            }
            if (t == 0) { g_top[bh * NTOP + it] = i2; winslot = s2; }
        }
        __syncthreads();
        if (t == winslot) myv = -FLT_MAX;
        __syncthreads();
    }
}

// ---------------- split-KV attention partials (register tiled) -------------
__global__ __launch_bounds__(256) void attn_partial(const float* __restrict__ Q,
                                                    const float* __restrict__ K,
                                                    const float* __restrict__ V) {
    __shared__ float sKT[64 * 68];     // K^T [d][k]; later reused as V [k][d]
    __shared__ float sQT[64 * 49];     // Q^T [d][u]
    __shared__ float sP[48 * 64];      // scores/probs [u][k] (rows 45-47 unused)
    __shared__ int sTop[NTOP];

    int t = threadIdx.x;
    int blk = blockIdx.x;
    int bh = blk >> 6;
    int sp = blk & 63;
    int k0 = sp * KPS;

    if (t < NTOP) sTop[t] = g_top[bh * NTOP + t];
    __syncthreads();

    // K tile (transposed into sKT[d][k])
    const float* Kp = K + ((size_t)bh * LSEQ + k0) * DIM;
    for (int i = t; i < 64 * 64; i += 256) {
        int k = i >> 6, d = i & 63;
        sKT[d * 68 + k] = Kp[i];
    }
    // Q rows gathered (transposed into sQT[d][u])
    for (int i = t; i < NTOP * 64; i += 256) {
        int u = i >> 6, d = i & 63;
        sQT[d * 49 + u] = Q[((size_t)bh * LSEQ + sTop[u]) * DIM + d];
    }
    __syncthreads();

    // scores: thread (tu,tk) -> 3u x 4k register tile
    int tk = t & 15, tu = t >> 4;
    {
        float acc[3][4] = {};
#pragma unroll 4
        for (int dd = 0; dd < 64; dd++) {
            float qv0 = sQT[dd * 49 + tu];
            float qv1 = sQT[dd * 49 + tu + 16];
            float qv2 = sQT[dd * 49 + tu + 32];
            float4 kv = *(const float4*)&sKT[dd * 68 + 4 * tk];
            acc[0][0] += qv0 * kv.x; acc[0][1] += qv0 * kv.y;
            acc[0][2] += qv0 * kv.z; acc[0][3] += qv0 * kv.w;
            acc[1][0] += qv1 * kv.x; acc[1][1] += qv1 * kv.y;
            acc[1][2] += qv1 * kv.z; acc[1][3] += qv1 * kv.w;
            acc[2][0] += qv2 * kv.x; acc[2][1] += qv2 * kv.y;
            acc[2][2] += qv2 * kv.z; acc[2][3] += qv2 * kv.w;
        }
#pragma unroll
        for (int r = 0; r < 3; r++) {
            int u = tu + 16 * r;
            if (u < NTOP) {
                int pos = sTop[u];
#pragma unroll
                for (int j = 0; j < 4; j++) {
                    int kg = k0 + 4 * tk + j;
                    sP[u * 64 + 4 * tk + j] =
                        (kg > pos) ? -FLT_MAX : acc[r][j] * 0.125f;
                }
            }
        }
    }
    __syncthreads();

    // V tile into sKT space as [k][d]  (K no longer needed)
    const float* Vp = V + ((size_t)bh * LSEQ + k0) * DIM;
    float* sV = sKT;
    for (int i = t; i < 64 * 64; i += 256) {
        int k = i >> 6, d = i & 63;
        sV[k * 68 + d] = Vp[i];
    }
    // softmax stats: warp per u
    {
        int w = t >> 5, lane = t & 31;
        for (int u = w; u < NTOP; u += 8) {
            float a = sP[u * 64 + lane];
            float b = sP[u * 64 + lane + 32];
            float m = fmaxf(a, b);
#pragma unroll
            for (int o = 16; o; o >>= 1)
                m = fmaxf(m, __shfl_xor_sync(0xffffffffu, m, o));
            float e0 = __expf(a - m);
            float e1 = __expf(b - m);
            float l = e0 + e1;
#pragma unroll
            for (int o = 16; o; o >>= 1)
                l += __shfl_xor_sync(0xffffffffu, l, o);
            sP[u * 64 + lane] = e0;
            sP[u * 64 + lane + 32] = e1;
            if (lane == 0) {
                g_pm[(bh * NSPLIT + sp) * NTOP + u] = m;
                g_pl[(bh * NSPLIT + sp) * NTOP + u] = l;
            }
        }
    }
    __syncthreads();

    // o-accum: thread (tu2,td) -> 3u x 4d register tile
    {
        int td = t & 15, tu2 = t >> 4;
        float oa[3][4] = {};
#pragma unroll 4
        for (int kk = 0; kk < 64; kk++) {
            float p0 = sP[(tu2) * 64 + kk];
            float p1 = sP[(tu2 + 16) * 64 + kk];
            float p2 = sP[(tu2 + 32) * 64 + kk];     // rows >=45: garbage, unused
            float4 vv = *(const float4*)&sV[kk * 68 + 4 * td];
            oa[0][0] += p0 * vv.x; oa[0][1] += p0 * vv.y;
            oa[0][2] += p0 * vv.z; oa[0][3] += p0 * vv.w;
            oa[1][0] += p1 * vv.x; oa[1][1] += p1 * vv.y;
            oa[1][2] += p1 * vv.z; oa[1][3] += p1 * vv.w;
            oa[2][0] += p2 * vv.x; oa[2][1] += p2 * vv.y;
            oa[2][2] += p2 * vv.z; oa[2][3] += p2 * vv.w;
        }
        float* po = g_po + (size_t)(bh * NSPLIT + sp) * NTOP * DIM;
#pragma unroll
        for (int r = 0; r < 3; r++) {
            int u = tu2 + 16 * r;
            if (u < NTOP) {
                float4 v4 = make_float4(oa[r][0], oa[r][1], oa[r][2], oa[r][3]);
                *(float4*)&po[u * DIM + 4 * td] = v4;
            }
        }
    }
}

// ---------------- combine partials + scatter ----------------
__global__ __launch_bounds__(64) void combine_kernel(float* __restrict__ out) {
    int blk = blockIdx.x;
    int bh = blk / NTOP;
    int u = blk % NTOP;
    int d = threadIdx.x;

    const float* pm = g_pm + bh * NSPLIT * NTOP + u;
    const float* pl = g_pl + bh * NSPLIT * NTOP + u;

    float m = -FLT_MAX;
#pragma unroll 4
    for (int sp = 0; sp < NSPLIT; sp++) m = fmaxf(m, pm[sp * NTOP]);

    float acc = 0.f, l = 0.f;
    const float* po = g_po + ((size_t)bh * NSPLIT * NTOP + u) * DIM + d;
#pragma unroll 4
    for (int sp = 0; sp < NSPLIT; sp++) {
        float wgt = __expf(pm[sp * NTOP] - m);
        l += wgt * pl[sp * NTOP];
        acc += wgt * po[(size_t)sp * NTOP * DIM];
    }
    int row = g_top[bh * NTOP + u];
    out[((size_t)bh * LSEQ + row) * DIM + d] = acc / l;
}

// ---------------- launch ----------------
extern "C" void kernel_launch(void* const* d_in, const int* in_sizes, int n_in,
                              void* d_out, int out_size) {
    const float* Q = (const float*)d_in[0];
    const float* K = (const float*)d_in[1];
    const float* V = (const float*)d_in[2];
    const int* idx = (const int*)d_in[3];
    float* out = (float*)d_out;

    convertK<<<BH * LSEQ * DIM / 1024, 256>>>(K);
    cumsum1<<<BH * 32, 256>>>(V);
    cumsum2<<<BH, 256>>>();
    cumsum3<<<BH * 32, 256>>>(V, out);

    computeM_approx<<<BH * 512, 256>>>(Q, idx);
    candidates<<<BH, 1024>>>();
    refineM<<<BH * 48, 256>>>(Q, K, idx);
    topk_final<<<BH, NCAND>>>();
    attn_partial<<<BH * NSPLIT, 256>>>(Q, K, V);
    combine_kernel<<<BH * NTOP, 64>>>(out);
}

// round 4
// speedup vs baseline: 1.3314x; 1.0137x over previous
#include <cuda_runtime.h>
#include <cuda_fp16.h>
#include <math.h>
#include <float.h>

// ProbSparse attention (Informer) B=2,H=8,L=4096,D=64, u=45.
// Round 4 (re-bench of R3): fp16 Q+K sampling w/ HFMA2, causal-pruned
// register-tiled attention (sorted-descending positions, slab-specialized),
// warp-scan cumsum.

#define BH      16
#define LSEQ    4096
#define DIM     64
#define NSAMP   45
#define NTOP    45
#define NCAND   384
#define NSPLIT  64
#define KPS     (LSEQ / NSPLIT)    // 64
#define NCHUNK  256
#define RPC     (LSEQ / NCHUNK)    // 16

// ---------------- device scratch ----------------
__device__ __half g_Kh[BH * LSEQ * DIM];             // 8 MB
__device__ __half g_Qh[BH * LSEQ * DIM];             // 8 MB
__device__ float  g_M[BH * LSEQ];
__device__ int    g_cand[BH * NCAND];
__device__ float  g_Mex[BH * NCAND];
__device__ int    g_top[BH * NTOP];                  // by-M order
__device__ int    g_tops[BH * NTOP];                 // position-descending
__device__ float  g_pm[BH * NSPLIT * NTOP];
__device__ float  g_pl[BH * NSPLIT * NTOP];
__device__ float  g_po[BH * NSPLIT * NTOP * DIM];
__device__ float  g_csum[BH * NCHUNK * DIM];

// ---------------- K & Q fp32 -> fp16 ----------------
__global__ __launch_bounds__(256) void convertKQ(const float* __restrict__ K,
                                                 const float* __restrict__ Q) {
    const int N4 = BH * LSEQ * DIM / 4;
    int i = blockIdx.x * 256 + threadIdx.x;
    const float* src = K;
    __half* dst = g_Kh;
    if (i >= N4) { i -= N4; src = Q; dst = g_Qh; }
    float4 v = ((const float4* __restrict__)src)[i];
    __half2 h0 = __floats2half2_rn(v.x, v.y);
    __half2 h1 = __floats2half2_rn(v.z, v.w);
    uint2 packed;
    packed.x = *(unsigned int*)&h0;
    packed.y = *(unsigned int*)&h1;
    ((uint2*)dst)[i] = packed;
}

// ---------------- cumsum pass 1: per-chunk column sums ----------------
__global__ __launch_bounds__(256) void cumsum1(const float* __restrict__ V) {
    int t = threadIdx.x, d = t & 63, cib = t >> 6;
    int blk = blockIdx.x, bh = blk >> 6;
    int chunk = (blk & 63) * 4 + cib;
    const float* p = V + ((size_t)bh * LSEQ + (size_t)chunk * RPC) * DIM + d;
    float s = 0.f;
#pragma unroll
    for (int r = 0; r < RPC; r++) s += p[r * DIM];
    g_csum[(bh * NCHUNK + chunk) * DIM + d] = s;
}

// ---------------- cumsum pass 2: warp-scan of 256 chunk sums ----------------
__global__ __launch_bounds__(1024) void cumsum2() {
    int blk = blockIdx.x;                  // BH*2
    int bh = blk >> 1;
    int d = (blk & 1) * 32 + (threadIdx.x >> 5);
    int lane = threadIdx.x & 31;
    float* base = g_csum + bh * NCHUNK * DIM + d;

    float ex[8];
    float run = 0.f;
#pragma unroll
    for (int j = 0; j < 8; j++) {
        float v = base[(8 * lane + j) * DIM];
        ex[j] = run;
        run += v;
    }
    float x = run;
#pragma unroll
    for (int o = 1; o < 32; o <<= 1) {
        float y = __shfl_up_sync(0xffffffffu, x, o);
        if (lane >= o) x += y;
    }
    float offset = x - run;                // exclusive prefix of warp totals
#pragma unroll
    for (int j = 0; j < 8; j++)
        base[(8 * lane + j) * DIM] = offset + ex[j];
}

// ---------------- cumsum pass 3: write inclusive cumsum ----------------
__global__ __launch_bounds__(256) void cumsum3(const float* __restrict__ V,
                                               float* __restrict__ out) {
    int t = threadIdx.x, d = t & 63, cib = t >> 6;
    int blk = blockIdx.x, bh = blk >> 6;
    int chunk = (blk & 63) * 4 + cib;
    const float* p = V + ((size_t)bh * LSEQ + (size_t)chunk * RPC) * DIM + d;
    float* o = out + ((size_t)bh * LSEQ + (size_t)chunk * RPC) * DIM + d;
    float acc = g_csum[(bh * NCHUNK + chunk) * DIM + d];
#pragma unroll
    for (int r = 0; r < RPC; r++) {
        acc += p[r * DIM];
        o[r * DIM] = acc;
    }
}

// ---------------- approx M: fp16 gather + HFMA2 ----------------
__global__ __launch_bounds__(256) void computeM_approx(const int* __restrict__ idx) {
    int w = threadIdx.x >> 5;
    int lane = threadIdx.x & 31;
    int r = lane >> 3;                 // row slot 0..3
    int sub = lane & 7;                // 16B slice within row
    int blk = blockIdx.x;
    int bh = blk >> 9;
    int q = (blk & 511) * 8 + w;

    uint4 qr = *(const uint4*)(g_Qh + ((size_t)bh * LSEQ + q) * DIM + sub * 8);
    __half2 q0 = *(__half2*)&qr.x, q1 = *(__half2*)&qr.y;
    __half2 q2 = *(__half2*)&qr.z, q3 = *(__half2*)&qr.w;

    const int* ip = idx + q * NSAMP;
    int i0 = ip[lane < NSAMP ? lane : 0];
    int i1 = ip[lane < (NSAMP - 32) ? 32 + lane : 0];

    const __half* Kbh = g_Kh + (size_t)bh * LSEQ * DIM;

    float mx = -FLT_MAX, sm = 0.f;

#pragma unroll
    for (int i = 0; i < 12; i++) {
        int kidx;
        if (i < 11) {
            int j = 4 * i + r;
            kidx = (i < 8) ? __shfl_sync(0xffffffffu, i0, j)
                           : __shfl_sync(0xffffffffu, i1, j - 32);
        } else {
            kidx = __shfl_sync(0xffffffffu, i1, 12);   // sample 44
        }
        uint4 kv = *(const uint4*)(Kbh + (size_t)kidx * DIM + sub * 8);
        __half2 acc = __hmul2(q0, *(__half2*)&kv.x);
        acc = __hfma2(q1, *(__half2*)&kv.y, acc);
        acc = __hfma2(q2, *(__half2*)&kv.z, acc);
        acc = __hfma2(q3, *(__half2*)&kv.w, acc);
#pragma unroll
        for (int o = 1; o <= 4; o <<= 1) {
            unsigned uu = __shfl_xor_sync(0xffffffffu, *(unsigned*)&acc, o);
            acc = __hadd2(acc, *(__half2*)&uu);
        }
        float2 f = __half22float2(acc);
        float p = f.x + f.y;
        if (i < 11 || r == 0) { mx = fmaxf(mx, p); sm += p; }
    }
    mx = fmaxf(mx, __shfl_xor_sync(0xffffffffu, mx, 8));
    mx = fmaxf(mx, __shfl_xor_sync(0xffffffffu, mx, 16));
    sm += __shfl_xor_sync(0xffffffffu, sm, 8);
    sm += __shfl_xor_sync(0xffffffffu, sm, 16);
    if (lane == 0)
        g_M[bh * LSEQ + q] = mx - sm * (1.0f / (float)LSEQ);
}

// ---------------- candidates: per-warp local top-12 ----------------
__global__ __launch_bounds__(1024) void candidates() {
    int bh = blockIdx.x;
    int t = threadIdx.x;
    int w = t >> 5, lane = t & 31;
    int base = w * 128;
    float v[4];
#pragma unroll
    for (int rr = 0; rr < 4; rr++)
        v[rr] = g_M[bh * LSEQ + base + lane + 32 * rr];

    for (int it = 0; it < 12; it++) {
        float bv = v[0];
        int bi = base + lane;
#pragma unroll
        for (int rr = 1; rr < 4; rr++) {
            float vv = v[rr];
            int ii = base + lane + 32 * rr;
            if (vv > bv) { bv = vv; bi = ii; }
        }
#pragma unroll
        for (int o = 16; o; o >>= 1) {
            float ov = __shfl_xor_sync(0xffffffffu, bv, o);
            int oi = __shfl_xor_sync(0xffffffffu, bi, o);
            if (ov > bv || (ov == bv && oi < bi)) { bv = ov; bi = oi; }
        }
        int loc = bi - base;
        if ((loc & 31) == lane) v[loc >> 5] = -FLT_MAX;
        if (lane == 0) g_cand[bh * NCAND + w * 12 + it] = bi;
    }
}

// ---------------- exact fp32 M for candidates ----------------
__global__ __launch_bounds__(256) void refineM(const float* __restrict__ Q,
                                               const float* __restrict__ K,
                                               const int* __restrict__ idx) {
    int w = threadIdx.x >> 5;
    int lane = threadIdx.x & 31;
    int blk = blockIdx.x;               // BH * 48
    int bh = blk / 48;
    int slot = (blk % 48) * 8 + w;
    int q = g_cand[bh * NCAND + slot];

    const float2* qp = (const float2*)(Q + ((size_t)bh * LSEQ + q) * DIM);
    float2 qv = qp[lane];
    const int* ip = idx + q * NSAMP;
    const float* Kbh = K + (size_t)bh * LSEQ * DIM;

    float mx = -FLT_MAX, sm = 0.f;
#pragma unroll 3
    for (int s = 0; s < NSAMP; s += 3) {
        int k0 = ip[s], k1 = ip[s + 1], k2 = ip[s + 2];
        float2 a = ((const float2*)(Kbh + (size_t)k0 * DIM))[lane];
        float2 b = ((const float2*)(Kbh + (size_t)k1 * DIM))[lane];
        float2 c = ((const float2*)(Kbh + (size_t)k2 * DIM))[lane];
        float p0 = qv.x * a.x + qv.y * a.y;
        float p1 = qv.x * b.x + qv.y * b.y;
        float p2 = qv.x * c.x + qv.y * c.y;
#pragma unroll
        for (int o = 16; o; o >>= 1) {
            p0 += __shfl_xor_sync(0xffffffffu, p0, o);
            p1 += __shfl_xor_sync(0xffffffffu, p1, o);
            p2 += __shfl_xor_sync(0xffffffffu, p2, o);
        }
        mx = fmaxf(mx, p0); sm += p0;
        mx = fmaxf(mx, p1); sm += p1;
        mx = fmaxf(mx, p2); sm += p2;
    }
    if (lane == 0)
        g_Mex[bh * NCAND + slot] = mx - sm * (1.0f / (float)LSEQ);
}

// ---------------- final exact top-45 + position-descending reorder ---------
__global__ __launch_bounds__(NCAND) void topk_final() {
    __shared__ float wv[12];
    __shared__ int wi[12], ws[12], winslot;
    int bh = blockIdx.x;
    int t = threadIdx.x;
    int lane = t & 31, w = t >> 5;

    float myv = g_Mex[bh * NCAND + t];
    int myi = g_cand[bh * NCAND + t];

    for (int it = 0; it < NTOP; it++) {
        float bv = myv; int bi = myi; int bs = t;
#pragma unroll
        for (int o = 16; o; o >>= 1) {
            float ov = __shfl_xor_sync(0xffffffffu, bv, o);
            int oi = __shfl_xor_sync(0xffffffffu, bi, o);
            int os = __shfl_xor_sync(0xffffffffu, bs, o);
            if (ov > bv || (ov == bv && oi < bi)) { bv = ov; bi = oi; bs = os; }
        }
        if (lane == 0) { wv[w] = bv; wi[w] = bi; ws[w] = bs; }
        __syncthreads();
        if (t < 32) {
            float v2 = (t < 12) ? wv[t] : -FLT_MAX;
            int i2 = (t < 12) ? wi[t] : 0x7fffffff;
            int s2 = (t < 12) ? ws[t] : 0;
#pragma unroll
            for (int o = 16; o; o >>= 1) {
                float ov = __shfl_xor_sync(0xffffffffu, v2, o);
                int oi = __shfl_xor_sync(0xffffffffu, i2, o);
                int os = __shfl_xor_sync(0xffffffffu, s2, o);
                if (ov > v2 || (ov == v2 && oi < i2)) { v2 = ov; i2 = oi; s2 = os; }
            }
            if (t == 0) { g_top[bh * NTOP + it] = i2; winslot = s2; }
        }
        __syncthreads();
        if (t == winslot) myv = -FLT_MAX;
        __syncthreads();
    }
    // reorder by position descending
    if (t < NTOP) {
        int pos = g_top[bh * NTOP + t];
        int rank = 0;
        for (int j = 0; j < NTOP; j++)
            rank += (g_top[bh * NTOP + j] > pos);
        g_tops[bh * NTOP + rank] = pos;
    }
}

// ---------------- attention tile helpers (slab-specialized) ----------------
template <int NS>
__device__ __forceinline__ void score_phase(const float* sQT, const float* sKT,
                                            float* sP, const int* sTop,
                                            int nact, int k0, int t) {
    int tk = t & 15, tu = t >> 4;
    float acc[NS][4];
#pragma unroll
    for (int r = 0; r < NS; r++)
#pragma unroll
        for (int j = 0; j < 4; j++) acc[r][j] = 0.f;
#pragma unroll 4
    for (int dd = 0; dd < 64; dd++) {
        float4 kv = *(const float4*)&sKT[dd * 68 + 4 * tk];
#pragma unroll
        for (int r = 0; r < NS; r++) {
            float qv = sQT[dd * 49 + tu + 16 * r];
            acc[r][0] += qv * kv.x; acc[r][1] += qv * kv.y;
            acc[r][2] += qv * kv.z; acc[r][3] += qv * kv.w;
        }
    }
#pragma unroll
    for (int r = 0; r < NS; r++) {
        int u = tu + 16 * r;
        if (u < nact) {
            int pos = sTop[u];
#pragma unroll
            for (int j = 0; j < 4; j++) {
                int kg = k0 + 4 * tk + j;
                sP[u * 64 + 4 * tk + j] = (kg > pos) ? -FLT_MAX : acc[r][j] * 0.125f;
            }
        }
    }
}

template <int NS>
__device__ __forceinline__ void pv_phase(const float* sP, const float* sV,
                                         float* po, int nact, int t) {
    int td = t & 15, tu = t >> 4;
    float oa[NS][4];
#pragma unroll
    for (int r = 0; r < NS; r++)
#pragma unroll
        for (int j = 0; j < 4; j++) oa[r][j] = 0.f;
#pragma unroll 4
    for (int kk = 0; kk < 64; kk++) {
        float4 vv = *(const float4*)&sV[kk * 68 + 4 * td];
#pragma unroll
        for (int r = 0; r < NS; r++) {
            float p = sP[(tu + 16 * r) * 64 + kk];
            oa[r][0] += p * vv.x; oa[r][1] += p * vv.y;
            oa[r][2] += p * vv.z; oa[r][3] += p * vv.w;
        }
    }
#pragma unroll
    for (int r = 0; r < NS; r++) {
        int u = tu + 16 * r;
        if (u < nact)
            *(float4*)&po[u * DIM + 4 * td] =
                make_float4(oa[r][0], oa[r][1], oa[r][2], oa[r][3]);
    }
}

// ---------------- split-KV attention partials ----------------
__global__ __launch_bounds__(256) void attn_partial(const float* __restrict__ Q,
                                                    const float* __restrict__ K,
                                                    const float* __restrict__ V) {
    __shared__ float sKT[64 * 68];     // K^T [d][k]; reused as V [k][d]
    __shared__ float sQT[64 * 49];     // Q^T [d][u]
    __shared__ float sP[48 * 64];
    __shared__ int sTop[NTOP];
    __shared__ int sNact;

    int t = threadIdx.x;
    int blk = blockIdx.x;
    int bh = blk >> 6;
    int sp = blk & 63;
    int k0 = sp * KPS;

    if (t < NTOP) sTop[t] = g_tops[bh * NTOP + t];
    if (t == 64) sNact = 0;
    __syncthreads();
    if (t < NTOP) {
        bool act = sTop[t] >= k0;
        bool nxt = (t + 1 < NTOP) ? (sTop[t + 1] >= k0) : false;
        if (act && !nxt) sNact = t + 1;
    }
    __syncthreads();
    int nact = sNact;
    if (nact == 0) {
        if (t < NTOP) {
            g_pm[(bh * NSPLIT + sp) * NTOP + t] = -FLT_MAX;
            g_pl[(bh * NSPLIT + sp) * NTOP + t] = 0.f;
        }
        return;
    }

    // K tile transposed into sKT[d][k]
    const float* Kp = K + ((size_t)bh * LSEQ + k0) * DIM;
    for (int i = t; i < 64 * 64; i += 256) {
        int k = i >> 6, d = i & 63;
        sKT[d * 68 + k] = Kp[i];
    }
    // active Q rows transposed into sQT[d][u]
    for (int i = t; i < nact * 64; i += 256) {
        int u = i >> 6, d = i & 63;
        sQT[d * 49 + u] = Q[((size_t)bh * LSEQ + sTop[u]) * DIM + d];
    }
    __syncthreads();

    int nslab = (nact + 15) >> 4;
    switch (nslab) {
        case 1: score_phase<1>(sQT, sKT, sP, sTop, nact, k0, t); break;
        case 2: score_phase<2>(sQT, sKT, sP, sTop, nact, k0, t); break;
        default: score_phase<3>(sQT, sKT, sP, sTop, nact, k0, t); break;
    }
    __syncthreads();

    // V tile into sKT space as [k][d]
    const float* Vp = V + ((size_t)bh * LSEQ + k0) * DIM;
    float* sV = sKT;
    for (int i = t; i < 64 * 64; i += 256) {
        int k = i >> 6, d = i & 63;
        sV[k * 68 + d] = Vp[i];
    }
    // softmax stats for active u; sentinels for inactive
    {
        int w = t >> 5, lane = t & 31;
        for (int u = w; u < nact; u += 8) {
            float a = sP[u * 64 + lane];
            float b = sP[u * 64 + lane + 32];
            float m = fmaxf(a, b);
#pragma unroll
            for (int o = 16; o; o >>= 1)
                m = fmaxf(m, __shfl_xor_sync(0xffffffffu, m, o));
            float e0 = __expf(a - m);
            float e1 = __expf(b - m);
            float l = e0 + e1;
#pragma unroll
            for (int o = 16; o; o >>= 1)
                l += __shfl_xor_sync(0xffffffffu, l, o);
            sP[u * 64 + lane] = e0;
            sP[u * 64 + lane + 32] = e1;
            if (lane == 0) {
                g_pm[(bh * NSPLIT + sp) * NTOP + u] = m;
                g_pl[(bh * NSPLIT + sp) * NTOP + u] = l;
            }
        }
        if (t >= nact && t < NTOP) {
            g_pm[(bh * NSPLIT + sp) * NTOP + t] = -FLT_MAX;
            g_pl[(bh * NSPLIT + sp) * NTOP + t] = 0.f;
        }
    }
    __syncthreads();

    float* po = g_po + (size_t)(bh * NSPLIT + sp) * NTOP * DIM;
    switch (nslab) {
        case 1: pv_phase<1>(sP, sV, po, nact, t); break;
        case 2: pv_phase<2>(sP, sV, po, nact, t); break;
        default: pv_phase<3>(sP, sV, po, nact, t); break;
    }
}

// ---------------- combine partials + scatter ----------------
__global__ __launch_bounds__(64) void combine_kernel(float* __restrict__ out) {
    int blk = blockIdx.x;
    int bh = blk / NTOP;
    int u = blk % NTOP;
    int d = threadIdx.x;

    const float* pm = g_pm + bh * NSPLIT * NTOP + u;
    const float* pl = g_pl + bh * NSPLIT * NTOP + u;

    float m = -FLT_MAX;
#pragma unroll 4
    for (int sp = 0; sp < NSPLIT; sp++) m = fmaxf(m, pm[sp * NTOP]);

    float acc = 0.f, l = 0.f;
    const float* po = g_po + ((size_t)bh * NSPLIT * NTOP + u) * DIM + d;
#pragma unroll 4
    for (int sp = 0; sp < NSPLIT; sp++) {
        float pmv = pm[sp * NTOP];
        if (pmv > -FLT_MAX) {
            float wgt = __expf(pmv - m);
            l += wgt * pl[sp * NTOP];
            acc += wgt * po[(size_t)sp * NTOP * DIM];
        }
    }
    int row = g_tops[bh * NTOP + u];
    out[((size_t)bh * LSEQ + row) * DIM + d] = acc / l;
}

// ---------------- launch ----------------
extern "C" void kernel_launch(void* const* d_in, const int* in_sizes, int n_in,
                              void* d_out, int out_size) {
    const float* Q = (const float*)d_in[0];
    const float* K = (const float*)d_in[1];
    const float* V = (const float*)d_in[2];
    const int* idx = (const int*)d_in[3];
    float* out = (float*)d_out;

    convertKQ<<<2 * BH * LSEQ * DIM / 1024, 256>>>(K, Q);
    cumsum1<<<BH * 64, 256>>>(V);
    cumsum2<<<BH * 2, 1024>>>();
    cumsum3<<<BH * 64, 256>>>(V, out);

    computeM_approx<<<BH * 512, 256>>>(idx);
    candidates<<<BH, 1024>>>();
    refineM<<<BH * 48, 256>>>(Q, K, idx);
    topk_final<<<BH, NCAND>>>();
    attn_partial<<<BH * NSPLIT, 256>>>(Q, K, V);
    combine_kernel<<<BH * NTOP, 64>>>(out);
}